// round 14
// baseline (speedup 1.0000x reference)
#include <cuda_runtime.h>
#include <cooperative_groups.h>
#include <cuda_fp16.h>
#include <cstdint>

namespace cg = cooperative_groups;

#define DK 512
#define MAXN 10048
#define MAXE 161000
#define NCTA 296
#define STAGES 3
#define GSMEM  (STAGES * 32768)

// ---------------- scratch ----------------------------------------------------
__device__ int    g_deg[MAXN];          // static zero-init; re-zeroed each run
__device__ int    g_rowptr[MAXN + 1];
__device__ int    g_cursor[MAXN];
__device__ int    g_csr[MAXE];
__device__ float  g_invdeg[MAXN];
__device__ __half g_xh  [(size_t)MAXN * DK];
__device__ __half g_aggh[(size_t)MAXN * DK];
__device__ __half g_h1h [(size_t)MAXN * DK];
__device__ __half g_h2h [(size_t)MAXN * DK];
__device__ __half g_yh  [(size_t)MAXN * 256];
__device__ float  g_qf  [(size_t)MAXN * 256];
__device__ __half g_wth[4 * 512 * 512 + 2 * 256 * 512];
__device__ float  g_zero[512];

// ---------------- helpers ------------------------------------------------
__device__ __forceinline__ uint32_t smem_u32(const void* p) {
    uint32_t a;
    asm("{ .reg .u64 t; cvta.to.shared.u64 t, %1; cvt.u32.u64 %0, t; }" : "=r"(a) : "l"(p));
    return a;
}
__device__ __forceinline__ void ldsm_x4(uint32_t* r, uint32_t addr) {
    asm volatile("ldmatrix.sync.aligned.m8n8.x4.shared.b16 {%0,%1,%2,%3}, [%4];"
                 : "=r"(r[0]), "=r"(r[1]), "=r"(r[2]), "=r"(r[3]) : "r"(addr));
}
__device__ __forceinline__ void mma_f16(float* d, const uint32_t* a, const uint32_t* b) {
    asm volatile("mma.sync.aligned.m16n8k16.row.col.f32.f16.f16.f32 "
                 "{%0,%1,%2,%3}, {%4,%5,%6,%7}, {%8,%9}, {%0,%1,%2,%3};"
                 : "+f"(d[0]), "+f"(d[1]), "+f"(d[2]), "+f"(d[3])
                 : "r"(a[0]), "r"(a[1]), "r"(a[2]), "r"(a[3]), "r"(b[0]), "r"(b[1]));
}
__device__ __forceinline__ void cp16(uint32_t dst, const void* src) {
    asm volatile("cp.async.cg.shared.global [%0], [%1], 16;" :: "r"(dst), "l"(src));
}
#define CP_COMMIT() asm volatile("cp.async.commit_group;" ::: "memory")
#define CP_WAIT1()  asm volatile("cp.async.wait_group 1;" ::: "memory")
#define CP_WAIT0()  asm volatile("cp.async.wait_group 0;" ::: "memory")

// ---------------- GEMM tile (proven R8 body, device-function form) -----------
template <bool DUAL>
__device__ __forceinline__ void gemm_tile(char* smem, int row0, int col0,
    const __half* __restrict__ A0, const __half* __restrict__ A1,
    const __half* __restrict__ B0, const __half* __restrict__ B1,
    const float* __restrict__ bias,
    const float* __restrict__ gamma, const float* __restrict__ beta,
    const float* __restrict__ mean,  const float* __restrict__ var,
    __half* __restrict__ outh, float* __restrict__ outf,
    int split, int N, int Hdim, int bnrelu)
{
    constexpr int NC = DUAL ? 16 : 8;
    const uint32_t sb = smem_u32(smem);
    const int t    = threadIdx.x;
    const int lane = t & 31, wid = t >> 5;
    const int warp_m = wid & 3;
    const int warp_n = wid >> 2;

    int lrow[4], lf8[4];
    uint32_t loff[4];
#pragma unroll
    for (int i = 0; i < 4; i++) {
        int idx = t + i * 256;
        lrow[i] = idx >> 3; lf8[i] = idx & 7;
        loff[i] = (uint32_t)lrow[i] * 128 + (uint32_t)((lf8[i] ^ (lrow[i] & 7)) << 4);
    }

    const int rin  = lane & 7;
    const int aGrp = (lane >> 3) & 1, aKhi = (lane >> 4) & 1;
    const int rA0  = warp_m * 32 + aGrp * 8 + rin;
    const uint32_t aO0 = (uint32_t)rA0 * 128;
    const uint32_t aO1 = (uint32_t)(rA0 + 16) * 128;
    const uint32_t aRm = (uint32_t)(rA0 & 7);
    const int bGrp = (lane >> 4) & 1, bKhi = (lane >> 3) & 1;
    const int rB   = warp_n * 64 + bGrp * 8 + rin;
    const uint32_t bRm = (uint32_t)(rB & 7);
    uint32_t bO[4];
#pragma unroll
    for (int p = 0; p < 4; p++) bO[p] = (uint32_t)(rB + p * 16) * 128;

    float d[2][8][4];
#pragma unroll
    for (int mt = 0; mt < 2; mt++)
#pragma unroll
        for (int nt = 0; nt < 8; nt++)
#pragma unroll
            for (int q = 0; q < 4; q++) d[mt][nt][q] = 0.f;

    auto load_stage = [&](int c) {
        const __half* As = (DUAL && c >= 8) ? A1 : A0;
        const __half* Bs = (DUAL && c >= 8) ? B1 : B0;
        const int kk = (c & 7) * 64;
        const uint32_t base = sb + (uint32_t)(c % STAGES) * 32768;
#pragma unroll
        for (int i = 0; i < 4; i++) {
            int gr = min(row0 + lrow[i], N - 1);
            cp16(base + loff[i],         As + (size_t)gr * DK + kk + lf8[i] * 8);
            cp16(base + 16384 + loff[i], Bs + (size_t)(col0 + lrow[i]) * DK + kk + lf8[i] * 8);
        }
        CP_COMMIT();
    };

    load_stage(0);
    load_stage(1);

    for (int c = 0; c < NC; c++) {
        if (c + 1 < NC) { CP_WAIT1(); } else { CP_WAIT0(); }
        __syncthreads();

        const uint32_t Ab = sb + (uint32_t)(c % STAGES) * 32768;
        const uint32_t Bb = Ab + 16384;
#pragma unroll
        for (int ks = 0; ks < 4; ks++) {
            uint32_t a[2][4], b[4][4];
            uint32_t ca = (((uint32_t)(ks * 2 + aKhi) ^ aRm) << 4);
            ldsm_x4(a[0], Ab + aO0 + ca);
            ldsm_x4(a[1], Ab + aO1 + ca);
            uint32_t cb = (((uint32_t)(ks * 2 + bKhi) ^ bRm) << 4);
#pragma unroll
            for (int p = 0; p < 4; p++) ldsm_x4(b[p], Bb + bO[p] + cb);
#pragma unroll
            for (int mt = 0; mt < 2; mt++)
#pragma unroll
                for (int p = 0; p < 4; p++) {
                    mma_f16(d[mt][p * 2 + 0], a[mt], &b[p][0]);
                    mma_f16(d[mt][p * 2 + 1], a[mt], &b[p][2]);
                }
        }
        if (c + 2 < NC) load_stage(c + 2);
    }

    const int g  = lane >> 2;
    const int cp = (lane & 3) * 2;
    const bool splitF32 = (split > 0) && (col0 >= split);
    const int ostride = (split > 0) ? split : Hdim;
#pragma unroll
    for (int nt = 0; nt < 8; nt++) {
        const int gc = col0 + warp_n * 64 + nt * 8 + cp;
        float s0 = 1.f, s1 = 1.f, h0 = bias[gc], h1 = bias[gc + 1];
        if (bnrelu) {
            float r0 = gamma[gc]     * rsqrtf(var[gc]     + 1e-5f);
            float r1 = gamma[gc + 1] * rsqrtf(var[gc + 1] + 1e-5f);
            h0 = (h0 - mean[gc])     * r0 + beta[gc];
            h1 = (h1 - mean[gc + 1]) * r1 + beta[gc + 1];
            s0 = r0; s1 = r1;
        }
        const int oc = splitF32 ? (gc - split) : gc;
#pragma unroll
        for (int mt = 0; mt < 2; mt++) {
            const int r_lo = row0 + warp_m * 32 + mt * 16 + g;
            const int r_hi = r_lo + 8;
            float v0 = d[mt][nt][0] * s0 + h0;
            float v1 = d[mt][nt][1] * s1 + h1;
            float v2 = d[mt][nt][2] * s0 + h0;
            float v3 = d[mt][nt][3] * s1 + h1;
            if (bnrelu) {
                v0 = fmaxf(v0, 0.f); v1 = fmaxf(v1, 0.f);
                v2 = fmaxf(v2, 0.f); v3 = fmaxf(v3, 0.f);
            }
            if (splitF32) {
                if (r_lo < N)
                    *reinterpret_cast<float2*>(outf + (size_t)r_lo * ostride + oc) = make_float2(v0, v1);
                if (r_hi < N)
                    *reinterpret_cast<float2*>(outf + (size_t)r_hi * ostride + oc) = make_float2(v2, v3);
            } else {
                if (r_lo < N)
                    *reinterpret_cast<__half2*>(outh + (size_t)r_lo * ostride + oc) = __floats2half2_rn(v0, v1);
                if (r_hi < N)
                    *reinterpret_cast<__half2*>(outh + (size_t)r_hi * ostride + oc) = __floats2half2_rn(v2, v3);
            }
        }
    }
}

// ---------------- aggregation row (proven R8 body) -----------------------------
template <int WIDTH>
__device__ __forceinline__ void agg_row(const __half* __restrict__ x,
                                        __half* __restrict__ outh, int dst, int t) {
    const int beg = g_rowptr[dst], end = g_rowptr[dst + 1];
    constexpr int STRIDE = WIDTH / 8;
    const uint4* xb = reinterpret_cast<const uint4*>(x);
    float acc[8];
#pragma unroll
    for (int q = 0; q < 8; q++) acc[q] = 0.f;
    int e = beg;
    for (; e + 4 <= end; e += 4) {
        int s0 = __ldg(&g_csr[e]);
        int s1 = __ldg(&g_csr[e + 1]);
        int s2 = __ldg(&g_csr[e + 2]);
        int s3 = __ldg(&g_csr[e + 3]);
        uint4 v0 = __ldg(xb + (size_t)s0 * STRIDE + t);
        uint4 v1 = __ldg(xb + (size_t)s1 * STRIDE + t);
        uint4 v2 = __ldg(xb + (size_t)s2 * STRIDE + t);
        uint4 v3 = __ldg(xb + (size_t)s3 * STRIDE + t);
        const uint4* vv[4] = {&v0, &v1, &v2, &v3};
#pragma unroll
        for (int j = 0; j < 4; j++) {
            const __half2* h = reinterpret_cast<const __half2*>(vv[j]);
#pragma unroll
            for (int q = 0; q < 4; q++) {
                float2 f = __half22float2(h[q]);
                acc[q * 2]     += f.x;
                acc[q * 2 + 1] += f.y;
            }
        }
    }
    for (; e < end; e++) {
        int s0 = __ldg(&g_csr[e]);
        uint4 v0 = __ldg(xb + (size_t)s0 * STRIDE + t);
        const __half2* h = reinterpret_cast<const __half2*>(&v0);
#pragma unroll
        for (int q = 0; q < 4; q++) {
            float2 f = __half22float2(h[q]);
            acc[q * 2]     += f.x;
            acc[q * 2 + 1] += f.y;
        }
    }
    const float s = g_invdeg[dst];
    __half2 h[4];
#pragma unroll
    for (int q = 0; q < 4; q++)
        h[q] = __floats2half2_rn(acc[q * 2] * s, acc[q * 2 + 1] * s);
    reinterpret_cast<uint4*>(outh)[(size_t)dst * STRIDE + t] = *reinterpret_cast<uint4*>(h);
}

__device__ __forceinline__ void agg_final_row(const __half* __restrict__ yh,
                                              const float* __restrict__ qf,
                                              const float* __restrict__ bias,
                                              float* __restrict__ out, int dst, int t) {
    const int beg = g_rowptr[dst], end = g_rowptr[dst + 1];
    const uint4* xb = reinterpret_cast<const uint4*>(yh);
    float acc[8];
#pragma unroll
    for (int q = 0; q < 8; q++) acc[q] = 0.f;
    int e = beg;
    for (; e + 4 <= end; e += 4) {
        int s0 = __ldg(&g_csr[e]);
        int s1 = __ldg(&g_csr[e + 1]);
        int s2 = __ldg(&g_csr[e + 2]);
        int s3 = __ldg(&g_csr[e + 3]);
        uint4 v0 = __ldg(xb + (size_t)s0 * 32 + t);
        uint4 v1 = __ldg(xb + (size_t)s1 * 32 + t);
        uint4 v2 = __ldg(xb + (size_t)s2 * 32 + t);
        uint4 v3 = __ldg(xb + (size_t)s3 * 32 + t);
        const uint4* vv[4] = {&v0, &v1, &v2, &v3};
#pragma unroll
        for (int j = 0; j < 4; j++) {
            const __half2* h = reinterpret_cast<const __half2*>(vv[j]);
#pragma unroll
            for (int q = 0; q < 4; q++) {
                float2 f = __half22float2(h[q]);
                acc[q * 2]     += f.x;
                acc[q * 2 + 1] += f.y;
            }
        }
    }
    for (; e < end; e++) {
        int s0 = __ldg(&g_csr[e]);
        uint4 v0 = __ldg(xb + (size_t)s0 * 32 + t);
        const __half2* h = reinterpret_cast<const __half2*>(&v0);
#pragma unroll
        for (int q = 0; q < 4; q++) {
            float2 f = __half22float2(h[q]);
            acc[q * 2]     += f.x;
            acc[q * 2 + 1] += f.y;
        }
    }
    const float s = g_invdeg[dst];
    const float* qrow = qf + (size_t)dst * 256 + t * 8;
    const float* brow = bias + t * 8;
    float4 q0 = *reinterpret_cast<const float4*>(qrow);
    float4 q1 = *reinterpret_cast<const float4*>(qrow + 4);
    float4 b0 = *reinterpret_cast<const float4*>(brow);
    float4 b1 = *reinterpret_cast<const float4*>(brow + 4);
    float* orow = out + (size_t)dst * 256 + t * 8;
    *reinterpret_cast<float4*>(orow) = make_float4(
        acc[0] * s + q0.x + b0.x, acc[1] * s + q0.y + b0.y,
        acc[2] * s + q0.z + b0.z, acc[3] * s + q0.w + b0.w);
    *reinterpret_cast<float4*>(orow + 4) = make_float4(
        acc[4] * s + q1.x + b1.x, acc[5] * s + q1.y + b1.y,
        acc[6] * s + q1.z + b1.z, acc[7] * s + q1.w + b1.w);
}

// ---------------- megakernel ---------------------------------------------------
struct Args {
    const float* x; const int* ei;
    const float* w[6];                    // wl1, wr1, wl2, wr2, wl3, wr3
    const float *b1, *b2, *b3;
    const float *bn1g, *bn1b, *bn1m, *bn1v;
    const float *bn2g, *bn2b, *bn2m, *bn2v;
    float* out;
    int N, E, n8;
};

__global__ __launch_bounds__(256, 2) void k_fused(Args a) {
    extern __shared__ char smem[];
    cg::grid_group grid = cg::this_grid();
    const int tid = threadIdx.x, bid = blockIdx.x;
    const int nB = gridDim.x;
    const int gtid = bid * 256 + tid, gsz = nB * 256;
    const int N = a.N, E = a.E;

    __half* wlt1 = g_wth;
    __half* wrt1 = g_wth + 512 * 512;
    __half* wlt2 = g_wth + 2 * 512 * 512;
    __half* wrt2 = g_wth + 3 * 512 * 512;
    __half* wlt3 = g_wth + 4 * 512 * 512;

    // ---- P0: degree histogram
    for (int e = gtid; e < E; e += gsz) atomicAdd(&g_deg[a.ei[E + e]], 1);
    grid.sync();

    // ---- P1: exclusive scan (CTA 0; 256 threads x 40 elems, two-pass)
    if (bid == 0) {
        __shared__ int ws[8];
        __shared__ int stot;
        const int base = tid * 40;
        int sum = 0;
#pragma unroll
        for (int j = 0; j < 40; j++) {
            int idx = base + j;
            sum += (idx < N) ? g_deg[idx] : 0;
        }
        int sc = sum;
        const int lane = tid & 31, w = tid >> 5;
#pragma unroll
        for (int o = 1; o < 32; o <<= 1) {
            int u = __shfl_up_sync(0xffffffffu, sc, o);
            if (lane >= o) sc += u;
        }
        if (lane == 31) ws[w] = sc;
        __syncthreads();
        if (tid == 0) {
            int run = 0;
#pragma unroll
            for (int j = 0; j < 8; j++) { int v = ws[j]; ws[j] = run; run += v; }
            stot = run;
        }
        __syncthreads();
        int run = (sc - sum) + ws[w];
#pragma unroll
        for (int j = 0; j < 40; j++) {
            int idx = base + j;
            if (idx < N) {
                int d = g_deg[idx];
                g_rowptr[idx] = run;
                g_invdeg[idx] = 1.0f / (float)max(d, 1);
                g_cursor[idx] = 0;
                run += d;
            }
        }
        if (tid == 255) g_rowptr[N] = stot;
    }
    grid.sync();

    // ---- P2: CSR fill + deg re-zero + x->fp16 + weight transposes
    for (int e = gtid; e < E; e += gsz) {
        int d = a.ei[E + e];
        int pos = atomicAdd(&g_cursor[d], 1);
        g_csr[g_rowptr[d] + pos] = a.ei[e];
    }
    for (int i = gtid; i < N; i += gsz) g_deg[i] = 0;
    for (int i = gtid; i < a.n8; i += gsz) {
        float4 lo = reinterpret_cast<const float4*>(a.x)[i * 2];
        float4 hi = reinterpret_cast<const float4*>(a.x)[i * 2 + 1];
        __half2 h[4];
        h[0] = __floats2half2_rn(lo.x, lo.y);
        h[1] = __floats2half2_rn(lo.z, lo.w);
        h[2] = __floats2half2_rn(hi.x, hi.y);
        h[3] = __floats2half2_rn(hi.z, hi.w);
        reinterpret_cast<uint4*>(g_xh)[i] = *reinterpret_cast<uint4*>(h);
    }
    {
        float (*tile)[33] = reinterpret_cast<float(*)[33]>(smem);
        const int tx = tid & 31, ty = tid >> 5;
        for (int tb = bid; tb < 1536; tb += nB) {
            const int m = tb >> 8;                       // matrix 0..5
            const float* W = a.w[m];
            __half* WT = g_wth + ((m < 4) ? (size_t)m * 512 * 512
                                          : (size_t)4 * 512 * 512 + (size_t)(m - 4) * 256 * 512);
            const int H = (m < 4) ? 512 : 256;
            const int k0 = (tb & 15) * 32, h0 = ((tb >> 4) & 15) * 32;
            __syncthreads();
            if (h0 < H) {
#pragma unroll
                for (int i = 0; i < 32; i += 8)
                    tile[ty + i][tx] = W[(size_t)(k0 + ty + i) * H + h0 + tx];
            }
            __syncthreads();
            if (h0 < H) {
#pragma unroll
                for (int i = 0; i < 32; i += 8)
                    WT[(size_t)(h0 + ty + i) * DK + k0 + tx] = __float2half_rn(tile[tx][ty + i]);
            }
        }
    }
    grid.sync();

    // ---- P3: aggregation layer 1
    {
        const int sub = tid >> 6, t64 = tid & 63;
        for (int row = bid * 4 + sub; row < N; row += nB * 4)
            agg_row<512>(g_xh, g_aggh, row, t64);
    }
    grid.sync();

    // ---- P4: GEMM layer 1
    for (int tile = bid; tile < 79 * 4; tile += nB) {
        __syncthreads();
        gemm_tile<true>(smem, (tile >> 2) * 128, (tile & 3) * 128,
                        g_aggh, g_xh, wlt1, wrt1, a.b1,
                        a.bn1g, a.bn1b, a.bn1m, a.bn1v,
                        g_h1h, nullptr, 0, N, 512, 1);
    }
    grid.sync();

    // ---- P5: aggregation layer 2
    {
        const int sub = tid >> 6, t64 = tid & 63;
        for (int row = bid * 4 + sub; row < N; row += nB * 4)
            agg_row<512>(g_h1h, g_aggh, row, t64);
    }
    grid.sync();

    // ---- P6: GEMM layer 2
    for (int tile = bid; tile < 79 * 4; tile += nB) {
        __syncthreads();
        gemm_tile<true>(smem, (tile >> 2) * 128, (tile & 3) * 128,
                        g_aggh, g_h1h, wlt2, wrt2, a.b2,
                        a.bn2g, a.bn2b, a.bn2m, a.bn2v,
                        g_h2h, nullptr, 0, N, 512, 1);
    }
    grid.sync();

    // ---- P7: GEMM layer 3 wide projection [yh | qf] = h2 @ [wl3 | wr3]
    for (int tile = bid; tile < 79 * 4; tile += nB) {
        __syncthreads();
        gemm_tile<false>(smem, (tile >> 2) * 128, (tile & 3) * 128,
                         g_h2h, nullptr, wlt3, nullptr, g_zero,
                         g_zero, g_zero, g_zero, g_zero,
                         g_yh, g_qf, 256, N, 512, 0);
    }
    grid.sync();

    // ---- P8: final: out = mean-agg(yh) + qf + b3
    {
        const int sub = tid >> 5, t32 = tid & 31;
        for (int row = bid * 8 + sub; row < N; row += nB * 8)
            agg_final_row(g_yh, g_qf, a.b3, a.out, row, t32);
    }
}

// ---------------- launch ------------------------------------------------------
extern "C" void kernel_launch(void* const* d_in, const int* in_sizes, int n_in,
                              void* d_out, int out_size)
{
    Args a;
    a.x   = (const float*)d_in[0];
    a.ei  = (const int*)  d_in[1];
    a.w[0] = (const float*)d_in[2];   // w_l1
    a.b1   = (const float*)d_in[3];
    a.w[1] = (const float*)d_in[4];   // w_r1
    a.bn1g = (const float*)d_in[5];
    a.bn1b = (const float*)d_in[6];
    a.bn1m = (const float*)d_in[7];
    a.bn1v = (const float*)d_in[8];
    a.w[2] = (const float*)d_in[9];   // w_l2
    a.b2   = (const float*)d_in[10];
    a.w[3] = (const float*)d_in[11];  // w_r2
    a.bn2g = (const float*)d_in[12];
    a.bn2b = (const float*)d_in[13];
    a.bn2m = (const float*)d_in[14];
    a.bn2v = (const float*)d_in[15];
    a.w[4] = (const float*)d_in[16];  // w_l3
    a.b3   = (const float*)d_in[17];
    a.w[5] = (const float*)d_in[18];  // w_r3
    a.out  = (float*)d_out;

    a.N  = in_sizes[0] / DK;
    a.E  = in_sizes[1] / 2;
    a.n8 = a.N * DK / 8;

    cudaFuncSetAttribute(k_fused, cudaFuncAttributeMaxDynamicSharedMemorySize, GSMEM);

    void* kargs[] = { &a };
    cudaLaunchCooperativeKernel((void*)k_fused, dim3(NCTA), dim3(256),
                                kargs, GSMEM, 0);
}

// round 15
// speedup vs baseline: 1.9190x; 1.9190x over previous
#include <cuda_runtime.h>
#include <cuda_fp16.h>
#include <cstdint>

#define DK 512
#define MAXN 10048
#define MAXE 161000

// ---------------- scratch ----------------------------------------------------
__device__ int    g_deg[MAXN];          // static zero-init; setup re-zeroes
__device__ int    g_rowptr[MAXN + 1];
__device__ int    g_cursor[MAXN];
__device__ int    g_csr[MAXE];
__device__ float  g_invdeg[MAXN];
__device__ __half g_xh  [(size_t)MAXN * DK];   // fp16 x
__device__ __half g_aggh[(size_t)MAXN * DK];   // fp16 aggregate (L1/L2)
__device__ __half g_h1h [(size_t)MAXN * DK];
__device__ __half g_h2h [(size_t)MAXN * DK];
__device__ __half g_yh  [(size_t)MAXN * 256];  // layer-3: h2@wl3 (fp16)
__device__ float  g_qf  [(size_t)MAXN * 256];  // layer-3: h2@wr3 (fp32)
__device__ __half g_wth[4 * 512 * 512 + 2 * 256 * 512];
__device__ float  g_zero[512];                 // static zeros (never written)

// ---------------- helpers ------------------------------------------------
__device__ __forceinline__ uint32_t smem_u32(const void* p) {
    uint32_t a;
    asm("{ .reg .u64 t; cvta.to.shared.u64 t, %1; cvt.u32.u64 %0, t; }" : "=r"(a) : "l"(p));
    return a;
}
__device__ __forceinline__ void ldsm_x4(uint32_t* r, uint32_t addr) {
    asm volatile("ldmatrix.sync.aligned.m8n8.x4.shared.b16 {%0,%1,%2,%3}, [%4];"
                 : "=r"(r[0]), "=r"(r[1]), "=r"(r[2]), "=r"(r[3]) : "r"(addr));
}
__device__ __forceinline__ void mma_f16(float* d, const uint32_t* a, const uint32_t* b) {
    asm volatile("mma.sync.aligned.m16n8k16.row.col.f32.f16.f16.f32 "
                 "{%0,%1,%2,%3}, {%4,%5,%6,%7}, {%8,%9}, {%0,%1,%2,%3};"
                 : "+f"(d[0]), "+f"(d[1]), "+f"(d[2]), "+f"(d[3])
                 : "r"(a[0]), "r"(a[1]), "r"(a[2]), "r"(a[3]), "r"(b[0]), "r"(b[1]));
}
__device__ __forceinline__ void cp16(uint32_t dst, const void* src) {
    asm volatile("cp.async.cg.shared.global [%0], [%1], 16;" :: "r"(dst), "l"(src));
}
#define CP_COMMIT() asm volatile("cp.async.commit_group;" ::: "memory")
#define CP_WAIT1()  asm volatile("cp.async.wait_group 1;" ::: "memory")
#define CP_WAIT0()  asm volatile("cp.async.wait_group 0;" ::: "memory")

// ---------------- CSR build --------------------------------------------------
__global__ void k_deg(const int* __restrict__ ei, int E) {
    int e = blockIdx.x * blockDim.x + threadIdx.x;
    if (e < E) atomicAdd(&g_deg[ei[E + e]], 1);
}

// Register-serial scan: thread t owns elements [10t, 10t+10). Serial prefix in
// registers, warp-shuffle scan over thread totals, warp scan over warp sums.
// Two __syncthreads total; bit-identical CSR to the 30-sync version.
#define SCH 10
__global__ void k_scan(int n) {
    __shared__ int ws[32];
    const int t = threadIdx.x, lane = t & 31, w = t >> 5;
    const int base = t * SCH;

    int d[SCH], pre[SCH];
    int sum = 0;
#pragma unroll
    for (int j = 0; j < SCH; j++) {
        int idx = base + j;
        d[j] = (idx < n) ? g_deg[idx] : 0;
        pre[j] = sum;
        sum += d[j];
    }
    int sc = sum;
#pragma unroll
    for (int o = 1; o < 32; o <<= 1) {
        int u = __shfl_up_sync(0xffffffffu, sc, o);
        if (lane >= o) sc += u;
    }
    if (lane == 31) ws[w] = sc;
    __syncthreads();
    if (w == 0) {
        int x2 = ws[lane];
#pragma unroll
        for (int o = 1; o < 32; o <<= 1) {
            int u = __shfl_up_sync(0xffffffffu, x2, o);
            if (lane >= o) x2 += u;
        }
        ws[lane] = x2;
    }
    __syncthreads();
    const int off = (sc - sum) + (w ? ws[w - 1] : 0);
#pragma unroll
    for (int j = 0; j < SCH; j++) {
        int idx = base + j;
        if (idx < n) {
            g_rowptr[idx] = off + pre[j];
            g_invdeg[idx] = 1.0f / (float)max(d[j], 1);
            g_cursor[idx] = 0;
        }
    }
    if (t == 1023) g_rowptr[n] = ws[31];
}

// ---------------- merged setup: CSR fill + deg re-zero + x->fp16 + transposes -
struct TP { const float* W; __half* WT; int H; };
struct TP6 { TP m[6]; };
__global__ void k_setup(const int* __restrict__ ei, int E, int n,
                        const float* __restrict__ x, __half* __restrict__ xh, int n8,
                        int nfill, TP6 tps) {
    __shared__ float tile[32][33];
    const int b = blockIdx.x;
    if (b < nfill) {
        int i = b * 256 + threadIdx.x;
        if (i < n) g_deg[i] = 0;   // restore invariant for next replay
        if (i < E) {
            int d = ei[E + i];
            int pos = atomicAdd(&g_cursor[d], 1);
            g_csr[g_rowptr[d] + pos] = ei[i];
        }
        if (i < n8) {
            float4 lo = reinterpret_cast<const float4*>(x)[i * 2];
            float4 hi = reinterpret_cast<const float4*>(x)[i * 2 + 1];
            __half2 h[4];
            h[0] = __floats2half2_rn(lo.x, lo.y);
            h[1] = __floats2half2_rn(lo.z, lo.w);
            h[2] = __floats2half2_rn(hi.x, hi.y);
            h[3] = __floats2half2_rn(hi.z, hi.w);
            reinterpret_cast<uint4*>(xh)[i] = *reinterpret_cast<uint4*>(h);
        }
    } else {
        const int tb = b - nfill;          // 0..1535
        const TP tp = tps.m[tb >> 8];
        const int H = tp.H;
        const int k0 = (tb & 15) * 32, h0 = ((tb >> 4) & 15) * 32;
        if (h0 >= H) return;
        const int tx = threadIdx.x & 31, ty = threadIdx.x >> 5;   // 32 x 8
#pragma unroll
        for (int i = 0; i < 32; i += 8)
            tile[ty + i][tx] = tp.W[(size_t)(k0 + ty + i) * H + h0 + tx];
        __syncthreads();
#pragma unroll
        for (int i = 0; i < 32; i += 8)
            tp.WT[(size_t)(h0 + ty + i) * DK + k0 + tx] = __float2half_rn(tile[tx][ty + i]);
    }
}

// ---------------- aggregation: fp16 input, HADD2 pair-tree, fp32 accumulate ---
// (exact body of the 168.4us-measured round-9 kernel)
template <int WIDTH>
__global__ void k_agg(const __half* __restrict__ x, __half* __restrict__ outh, int n) {
    int dst = blockIdx.x;
    if (dst >= n) return;
    const int beg = g_rowptr[dst], end = g_rowptr[dst + 1];
    const int t = threadIdx.x;
    constexpr int STRIDE = WIDTH / 8;
    const uint4* xb = reinterpret_cast<const uint4*>(x);
    float acc[8];
#pragma unroll
    for (int q = 0; q < 8; q++) acc[q] = 0.f;

    int e = beg;
    for (; e + 4 <= end; e += 4) {
        int s0 = __ldg(&g_csr[e]);
        int s1 = __ldg(&g_csr[e + 1]);
        int s2 = __ldg(&g_csr[e + 2]);
        int s3 = __ldg(&g_csr[e + 3]);
        uint4 v0 = __ldg(xb + (size_t)s0 * STRIDE + t);
        uint4 v1 = __ldg(xb + (size_t)s1 * STRIDE + t);
        uint4 v2 = __ldg(xb + (size_t)s2 * STRIDE + t);
        uint4 v3 = __ldg(xb + (size_t)s3 * STRIDE + t);
        const __half2* h0 = reinterpret_cast<const __half2*>(&v0);
        const __half2* h1 = reinterpret_cast<const __half2*>(&v1);
        const __half2* h2 = reinterpret_cast<const __half2*>(&v2);
        const __half2* h3 = reinterpret_cast<const __half2*>(&v3);
#pragma unroll
        for (int q = 0; q < 4; q++) {
            __half2 s01 = __hadd2(h0[q], h1[q]);   // one fp16 rounding per pair
            __half2 s23 = __hadd2(h2[q], h3[q]);
            float2 f0 = __half22float2(s01);
            float2 f1 = __half22float2(s23);
            acc[q * 2]     += f0.x + f1.x;
            acc[q * 2 + 1] += f0.y + f1.y;
        }
    }
    for (; e < end; e++) {
        int s0 = __ldg(&g_csr[e]);
        uint4 v0 = __ldg(xb + (size_t)s0 * STRIDE + t);
        const __half2* h = reinterpret_cast<const __half2*>(&v0);
#pragma unroll
        for (int q = 0; q < 4; q++) {
            float2 f = __half22float2(h[q]);
            acc[q * 2]     += f.x;
            acc[q * 2 + 1] += f.y;
        }
    }
    const float s = g_invdeg[dst];
    __half2 h[4];
#pragma unroll
    for (int q = 0; q < 4; q++)
        h[q] = __floats2half2_rn(acc[q * 2] * s, acc[q * 2 + 1] * s);
    reinterpret_cast<uint4*>(outh)[(size_t)dst * STRIDE + t] = *reinterpret_cast<uint4*>(h);
}

// ---------------- final aggregation: out = mean(yh[src]) + qf[dst] + b3 -------
__global__ void k_agg_final(const __half* __restrict__ yh, const float* __restrict__ qf,
                            const float* __restrict__ bias, float* __restrict__ out, int n) {
    int dst = blockIdx.x;
    if (dst >= n) return;
    const int beg = g_rowptr[dst], end = g_rowptr[dst + 1];
    const int t = threadIdx.x;           // 32 threads, 8 vals each (WIDTH 256)
    const uint4* xb = reinterpret_cast<const uint4*>(yh);
    float acc[8];
#pragma unroll
    for (int q = 0; q < 8; q++) acc[q] = 0.f;

    int e = beg;
    for (; e + 4 <= end; e += 4) {
        int s0 = __ldg(&g_csr[e]);
        int s1 = __ldg(&g_csr[e + 1]);
        int s2 = __ldg(&g_csr[e + 2]);
        int s3 = __ldg(&g_csr[e + 3]);
        uint4 v0 = __ldg(xb + (size_t)s0 * 32 + t);
        uint4 v1 = __ldg(xb + (size_t)s1 * 32 + t);
        uint4 v2 = __ldg(xb + (size_t)s2 * 32 + t);
        uint4 v3 = __ldg(xb + (size_t)s3 * 32 + t);
        const __half2* h0 = reinterpret_cast<const __half2*>(&v0);
        const __half2* h1 = reinterpret_cast<const __half2*>(&v1);
        const __half2* h2 = reinterpret_cast<const __half2*>(&v2);
        const __half2* h3 = reinterpret_cast<const __half2*>(&v3);
#pragma unroll
        for (int q = 0; q < 4; q++) {
            __half2 s01 = __hadd2(h0[q], h1[q]);
            __half2 s23 = __hadd2(h2[q], h3[q]);
            float2 f0 = __half22float2(s01);
            float2 f1 = __half22float2(s23);
            acc[q * 2]     += f0.x + f1.x;
            acc[q * 2 + 1] += f0.y + f1.y;
        }
    }
    for (; e < end; e++) {
        int s0 = __ldg(&g_csr[e]);
        uint4 v0 = __ldg(xb + (size_t)s0 * 32 + t);
        const __half2* h = reinterpret_cast<const __half2*>(&v0);
#pragma unroll
        for (int q = 0; q < 4; q++) {
            float2 f = __half22float2(h[q]);
            acc[q * 2]     += f.x;
            acc[q * 2 + 1] += f.y;
        }
    }
    const float s = g_invdeg[dst];
    const float* qrow = qf + (size_t)dst * 256 + t * 8;
    const float* brow = bias + t * 8;
    float4 q0 = *reinterpret_cast<const float4*>(qrow);
    float4 q1 = *reinterpret_cast<const float4*>(qrow + 4);
    float4 b0 = *reinterpret_cast<const float4*>(brow);
    float4 b1 = *reinterpret_cast<const float4*>(brow + 4);
    float* orow = out + (size_t)dst * 256 + t * 8;
    *reinterpret_cast<float4*>(orow) = make_float4(
        acc[0] * s + q0.x + b0.x, acc[1] * s + q0.y + b0.y,
        acc[2] * s + q0.z + b0.z, acc[3] * s + q0.w + b0.w);
    *reinterpret_cast<float4*>(orow + 4) = make_float4(
        acc[4] * s + q1.x + b1.x, acc[5] * s + q1.y + b1.y,
        acc[6] * s + q1.z + b1.z, acc[7] * s + q1.w + b1.w);
}

// ---------------- fp16 mma.sync GEMM, cp.async 3-stage (proven R8 config) -----
#define STAGES 3
#define GSMEM  (STAGES * 32768)

template <bool DUAL>
__global__ __launch_bounds__(256, 2)
void k_gemm(const __half* __restrict__ A0, const __half* __restrict__ A1,
            const __half* __restrict__ B0, const __half* __restrict__ B1,
            const float* __restrict__ bias,
            const float* __restrict__ gamma, const float* __restrict__ beta,
            const float* __restrict__ mean,  const float* __restrict__ var,
            __half* __restrict__ outh, float* __restrict__ outf,
            int split, int N, int Hdim, int bnrelu)
{
    constexpr int NC = DUAL ? 16 : 8;
    extern __shared__ char smem[];
    const uint32_t sb = smem_u32(smem);
    const int t    = threadIdx.x;
    const int lane = t & 31, wid = t >> 5;
    const int warp_m = wid & 3;
    const int warp_n = wid >> 2;
    const int row0 = blockIdx.x * 128;
    const int col0 = blockIdx.y * 128;

    int lrow[4], lf8[4];
    uint32_t loff[4];
#pragma unroll
    for (int i = 0; i < 4; i++) {
        int idx = t + i * 256;
        lrow[i] = idx >> 3; lf8[i] = idx & 7;
        loff[i] = (uint32_t)lrow[i] * 128 + (uint32_t)((lf8[i] ^ (lrow[i] & 7)) << 4);
    }

    const int rin  = lane & 7;
    const int aGrp = (lane >> 3) & 1, aKhi = (lane >> 4) & 1;
    const int rA0  = warp_m * 32 + aGrp * 8 + rin;
    const uint32_t aO0 = (uint32_t)rA0 * 128;
    const uint32_t aO1 = (uint32_t)(rA0 + 16) * 128;
    const uint32_t aRm = (uint32_t)(rA0 & 7);
    const int bGrp = (lane >> 4) & 1, bKhi = (lane >> 3) & 1;
    const int rB   = warp_n * 64 + bGrp * 8 + rin;
    const uint32_t bRm = (uint32_t)(rB & 7);
    uint32_t bO[4];
#pragma unroll
    for (int p = 0; p < 4; p++) bO[p] = (uint32_t)(rB + p * 16) * 128;

    float d[2][8][4];
#pragma unroll
    for (int mt = 0; mt < 2; mt++)
#pragma unroll
        for (int nt = 0; nt < 8; nt++)
#pragma unroll
            for (int q = 0; q < 4; q++) d[mt][nt][q] = 0.f;

    auto load_stage = [&](int c) {
        const __half* As = (DUAL && c >= 8) ? A1 : A0;
        const __half* Bs = (DUAL && c >= 8) ? B1 : B0;
        const int kk = (c & 7) * 64;
        const uint32_t base = sb + (uint32_t)(c % STAGES) * 32768;
#pragma unroll
        for (int i = 0; i < 4; i++) {
            int gr = min(row0 + lrow[i], N - 1);
            cp16(base + loff[i],         As + (size_t)gr * DK + kk + lf8[i] * 8);
            cp16(base + 16384 + loff[i], Bs + (size_t)(col0 + lrow[i]) * DK + kk + lf8[i] * 8);
        }
        CP_COMMIT();
    };

    load_stage(0);
    load_stage(1);

    for (int c = 0; c < NC; c++) {
        if (c + 1 < NC) { CP_WAIT1(); } else { CP_WAIT0(); }
        __syncthreads();

        const uint32_t Ab = sb + (uint32_t)(c % STAGES) * 32768;
        const uint32_t Bb = Ab + 16384;
#pragma unroll
        for (int ks = 0; ks < 4; ks++) {
            uint32_t a[2][4], b[4][4];
            uint32_t ca = (((uint32_t)(ks * 2 + aKhi) ^ aRm) << 4);
            ldsm_x4(a[0], Ab + aO0 + ca);
            ldsm_x4(a[1], Ab + aO1 + ca);
            uint32_t cb = (((uint32_t)(ks * 2 + bKhi) ^ bRm) << 4);
#pragma unroll
            for (int p = 0; p < 4; p++) ldsm_x4(b[p], Bb + bO[p] + cb);
#pragma unroll
            for (int mt = 0; mt < 2; mt++)
#pragma unroll
                for (int p = 0; p < 4; p++) {
                    mma_f16(d[mt][p * 2 + 0], a[mt], &b[p][0]);
                    mma_f16(d[mt][p * 2 + 1], a[mt], &b[p][2]);
                }
        }
        if (c + 2 < NC) load_stage(c + 2);
    }

    const int g  = lane >> 2;
    const int cp = (lane & 3) * 2;
    const bool splitF32 = (split > 0) && (col0 >= split);   // uniform per CTA
    const int ostride = (split > 0) ? split : Hdim;
#pragma unroll
    for (int nt = 0; nt < 8; nt++) {
        const int gc = col0 + warp_n * 64 + nt * 8 + cp;
        float s0 = 1.f, s1 = 1.f, h0 = bias[gc], h1 = bias[gc + 1];
        if (bnrelu) {
            float r0 = gamma[gc]     * rsqrtf(var[gc]     + 1e-5f);
            float r1 = gamma[gc + 1] * rsqrtf(var[gc + 1] + 1e-5f);
            h0 = (h0 - mean[gc])     * r0 + beta[gc];
            h1 = (h1 - mean[gc + 1]) * r1 + beta[gc + 1];
            s0 = r0; s1 = r1;
        }
        const int oc = splitF32 ? (gc - split) : gc;
#pragma unroll
        for (int mt = 0; mt < 2; mt++) {
            const int r_lo = row0 + warp_m * 32 + mt * 16 + g;
            const int r_hi = r_lo + 8;
            float v0 = d[mt][nt][0] * s0 + h0;
            float v1 = d[mt][nt][1] * s1 + h1;
            float v2 = d[mt][nt][2] * s0 + h0;
            float v3 = d[mt][nt][3] * s1 + h1;
            if (bnrelu) {
                v0 = fmaxf(v0, 0.f); v1 = fmaxf(v1, 0.f);
                v2 = fmaxf(v2, 0.f); v3 = fmaxf(v3, 0.f);
            }
            if (splitF32) {
                if (r_lo < N)
                    *reinterpret_cast<float2*>(outf + (size_t)r_lo * ostride + oc) = make_float2(v0, v1);
                if (r_hi < N)
                    *reinterpret_cast<float2*>(outf + (size_t)r_hi * ostride + oc) = make_float2(v2, v3);
            } else {
                if (r_lo < N)
                    *reinterpret_cast<__half2*>(outh + (size_t)r_lo * ostride + oc) = __floats2half2_rn(v0, v1);
                if (r_hi < N)
                    *reinterpret_cast<__half2*>(outh + (size_t)r_hi * ostride + oc) = __floats2half2_rn(v2, v3);
            }
        }
    }
}

// ---------------- launch ------------------------------------------------------
extern "C" void kernel_launch(void* const* d_in, const int* in_sizes, int n_in,
                              void* d_out, int out_size)
{
    const float* x     = (const float*)d_in[0];
    const int*   ei    = (const int*)  d_in[1];
    const float* w_l1  = (const float*)d_in[2];
    const float* b1    = (const float*)d_in[3];
    const float* w_r1  = (const float*)d_in[4];
    const float* bn1_g = (const float*)d_in[5];
    const float* bn1_b = (const float*)d_in[6];
    const float* bn1_m = (const float*)d_in[7];
    const float* bn1_v = (const float*)d_in[8];
    const float* w_l2  = (const float*)d_in[9];
    const float* b2    = (const float*)d_in[10];
    const float* w_r2  = (const float*)d_in[11];
    const float* bn2_g = (const float*)d_in[12];
    const float* bn2_b = (const float*)d_in[13];
    const float* bn2_m = (const float*)d_in[14];
    const float* bn2_v = (const float*)d_in[15];
    const float* w_l3  = (const float*)d_in[16];
    const float* b3    = (const float*)d_in[17];
    const float* w_r3  = (const float*)d_in[18];
    float* out = (float*)d_out;

    const int N = in_sizes[0] / DK;
    const int E = in_sizes[1] / 2;
    const int O = out_size / N;   // 256

    __half *xh, *aggh, *h1h, *h2h, *yh, *wth;
    float *qf, *zero;
    cudaGetSymbolAddress((void**)&xh,   g_xh);
    cudaGetSymbolAddress((void**)&aggh, g_aggh);
    cudaGetSymbolAddress((void**)&h1h,  g_h1h);
    cudaGetSymbolAddress((void**)&h2h,  g_h2h);
    cudaGetSymbolAddress((void**)&yh,   g_yh);
    cudaGetSymbolAddress((void**)&qf,   g_qf);
    cudaGetSymbolAddress((void**)&wth,  g_wth);
    cudaGetSymbolAddress((void**)&zero, g_zero);
    __half* wlt1 = wth;
    __half* wrt1 = wth + 512 * 512;
    __half* wlt2 = wth + 2 * 512 * 512;
    __half* wrt2 = wth + 3 * 512 * 512;
    __half* wlt3 = wth + 4 * 512 * 512;             // rows 0-255 of wide B
    __half* wrt3 = wth + 4 * 512 * 512 + 256 * 512; // rows 256-511 (contiguous)

    cudaFuncSetAttribute(k_gemm<true>,  cudaFuncAttributeMaxDynamicSharedMemorySize, GSMEM);
    cudaFuncSetAttribute(k_gemm<false>, cudaFuncAttributeMaxDynamicSharedMemorySize, GSMEM);

    const int n8 = N * DK / 8;
    const int nfill = (max(E, n8) + 255) / 256;

    // 1-3: CSR build + x->fp16 + weight transposes
    k_deg <<<(E + 255) / 256, 256>>>(ei, E);
    k_scan<<<1, 1024>>>(N);
    TP6 tps = {{ {w_l1, wlt1, 512}, {w_r1, wrt1, 512},
                 {w_l2, wlt2, 512}, {w_r2, wrt2, 512},
                 {w_l3, wlt3, 256}, {w_r3, wrt3, 256} }};
    k_setup<<<nfill + 6 * 256, 256>>>(ei, E, N, x, xh, n8, nfill, tps);

    // 4 (profiled): aggregation layer 1
    k_agg<512><<<N, 64>>>(xh, aggh, N);

    const int mt = (N + 127) / 128;
    dim3 gH(mt, 512 / 128);

    // 5: layer 1
    k_gemm<true><<<gH, 256, GSMEM>>>(aggh, xh, wlt1, wrt1, b1,
                                     bn1_g, bn1_b, bn1_m, bn1_v,
                                     h1h, nullptr, 0, N, 512, 1);
    // 6-7: layer 2
    k_agg<512><<<N, 64>>>(h1h, aggh, N);
    k_gemm<true><<<gH, 256, GSMEM>>>(aggh, h1h, wlt2, wrt2, b2,
                                     bn2_g, bn2_b, bn2_m, bn2_v,
                                     h2h, nullptr, 0, N, 512, 1);
    // 8: layer 3 wide projection: [yh | qf] = h2 @ [wl3 | wr3]
    k_gemm<false><<<gH, 256, GSMEM>>>(h2h, nullptr, wlt3, nullptr, zero,
                                      zero, zero, zero, zero,
                                      yh, qf, 256, N, 512, 0);
    // 9: out = mean-agg(yh) + qf + b3
    k_agg_final<<<N, 32>>>(yh, qf, b3, out, N);
}

// round 16
// speedup vs baseline: 2.0272x; 1.0564x over previous
#include <cuda_runtime.h>
#include <cuda_fp16.h>
#include <cstdint>

#define DK 512
#define MAXN 10048
#define MAXE 161000

// ---------------- scratch ----------------------------------------------------
__device__ int    g_deg[MAXN];          // static zero-init; setup re-zeroes
__device__ int    g_rowptr[MAXN + 1];
__device__ int    g_cursor[MAXN];
__device__ int    g_csr[MAXE];
__device__ float  g_invdeg[MAXN];
__device__ __half g_xh  [(size_t)MAXN * DK];   // fp16 x
__device__ __half g_aggh[(size_t)MAXN * DK];   // fp16 aggregate (L1/L2)
__device__ __half g_h1h [(size_t)MAXN * DK];
__device__ __half g_h2h [(size_t)MAXN * DK];
__device__ __half g_yh  [(size_t)MAXN * 256];  // layer-3: h2@wl3 (fp16)
__device__ float  g_qf  [(size_t)MAXN * 256];  // layer-3: h2@wr3 (fp32)
__device__ __half g_wth[4 * 512 * 512 + 2 * 256 * 512];
__device__ float  g_zero[512];                 // static zeros (never written)

// ---------------- helpers ------------------------------------------------
__device__ __forceinline__ uint32_t smem_u32(const void* p) {
    uint32_t a;
    asm("{ .reg .u64 t; cvta.to.shared.u64 t, %1; cvt.u32.u64 %0, t; }" : "=r"(a) : "l"(p));
    return a;
}
__device__ __forceinline__ void ldsm_x4(uint32_t* r, uint32_t addr) {
    asm volatile("ldmatrix.sync.aligned.m8n8.x4.shared.b16 {%0,%1,%2,%3}, [%4];"
                 : "=r"(r[0]), "=r"(r[1]), "=r"(r[2]), "=r"(r[3]) : "r"(addr));
}
__device__ __forceinline__ void mma_f16(float* d, const uint32_t* a, const uint32_t* b) {
    asm volatile("mma.sync.aligned.m16n8k16.row.col.f32.f16.f16.f32 "
                 "{%0,%1,%2,%3}, {%4,%5,%6,%7}, {%8,%9}, {%0,%1,%2,%3};"
                 : "+f"(d[0]), "+f"(d[1]), "+f"(d[2]), "+f"(d[3])
                 : "r"(a[0]), "r"(a[1]), "r"(a[2]), "r"(a[3]), "r"(b[0]), "r"(b[1]));
}
__device__ __forceinline__ void cp16(uint32_t dst, const void* src) {
    asm volatile("cp.async.cg.shared.global [%0], [%1], 16;" :: "r"(dst), "l"(src));
}
#define CP_COMMIT() asm volatile("cp.async.commit_group;" ::: "memory")
#define CP_WAIT1()  asm volatile("cp.async.wait_group 1;" ::: "memory")
#define CP_WAIT0()  asm volatile("cp.async.wait_group 0;" ::: "memory")

// ---------------- CSR build --------------------------------------------------
__global__ void k_deg(const int* __restrict__ ei, int E) {
    int e = blockIdx.x * blockDim.x + threadIdx.x;
    if (e < E) atomicAdd(&g_deg[ei[E + e]], 1);
}
__global__ void k_scan(int n) {
    __shared__ int ws[32];
    __shared__ int s_carry;
    const int t = threadIdx.x, lane = t & 31, w = t >> 5;
    if (t == 0) s_carry = 0;
    __syncthreads();
    for (int base = 0; base < n; base += 1024) {
        int idx = base + t;
        int v = (idx < n) ? g_deg[idx] : 0;
        int sc = v;
#pragma unroll
        for (int o = 1; o < 32; o <<= 1) {
            int u = __shfl_up_sync(0xffffffffu, sc, o);
            if (lane >= o) sc += u;
        }
        if (lane == 31) ws[w] = sc;
        __syncthreads();
        if (w == 0) {
            int x2 = ws[lane];
#pragma unroll
            for (int o = 1; o < 32; o <<= 1) {
                int u = __shfl_up_sync(0xffffffffu, x2, o);
                if (lane >= o) x2 += u;
            }
            ws[lane] = x2;
        }
        __syncthreads();
        int carry = s_carry;
        int add = carry + (w ? ws[w - 1] : 0);
        if (idx < n) {
            g_rowptr[idx] = add + sc - v;
            g_invdeg[idx] = 1.0f / (float)max(v, 1);
            g_cursor[idx] = 0;
        }
        __syncthreads();
        if (t == 0) s_carry = carry + ws[31];
        __syncthreads();
    }
    if (t == 0) g_rowptr[n] = s_carry;
}

// ---------------- merged setup: CSR fill + deg re-zero + x->fp16 + transposes -
struct TP { const float* W; __half* WT; int H; };
struct TP6 { TP m[6]; };
__global__ void k_setup(const int* __restrict__ ei, int E, int n,
                        const float* __restrict__ x, __half* __restrict__ xh, int n8,
                        int nfill, TP6 tps) {
    __shared__ float tile[32][33];
    const int b = blockIdx.x;
    if (b < nfill) {
        int i = b * 256 + threadIdx.x;
        if (i < n) g_deg[i] = 0;   // restore invariant for next replay
        if (i < E) {
            int d = ei[E + i];
            int pos = atomicAdd(&g_cursor[d], 1);
            g_csr[g_rowptr[d] + pos] = ei[i];
        }
        if (i < n8) {
            float4 lo = reinterpret_cast<const float4*>(x)[i * 2];
            float4 hi = reinterpret_cast<const float4*>(x)[i * 2 + 1];
            __half2 h[4];
            h[0] = __floats2half2_rn(lo.x, lo.y);
            h[1] = __floats2half2_rn(lo.z, lo.w);
            h[2] = __floats2half2_rn(hi.x, hi.y);
            h[3] = __floats2half2_rn(hi.z, hi.w);
            reinterpret_cast<uint4*>(xh)[i] = *reinterpret_cast<uint4*>(h);
        }
    } else {
        const int tb = b - nfill;          // 0..1535
        const TP tp = tps.m[tb >> 8];
        const int H = tp.H;
        const int k0 = (tb & 15) * 32, h0 = ((tb >> 4) & 15) * 32;
        if (h0 >= H) return;
        const int tx = threadIdx.x & 31, ty = threadIdx.x >> 5;   // 32 x 8
#pragma unroll
        for (int i = 0; i < 32; i += 8)
            tile[ty + i][tx] = tp.W[(size_t)(k0 + ty + i) * H + h0 + tx];
        __syncthreads();
#pragma unroll
        for (int i = 0; i < 32; i += 8)
            tp.WT[(size_t)(h0 + ty + i) * DK + k0 + tx] = __float2half_rn(tile[tx][ty + i]);
    }
}

// ---------------- aggregation: fp16 input, fp32 accumulate (proven 16.5us) ----
template <int WIDTH>
__global__ void k_agg(const __half* __restrict__ x, __half* __restrict__ outh, int n) {
    int dst = blockIdx.x;
    if (dst >= n) return;
    const int beg = g_rowptr[dst], end = g_rowptr[dst + 1];
    const int t = threadIdx.x;
    constexpr int STRIDE = WIDTH / 8;
    const uint4* xb = reinterpret_cast<const uint4*>(x);
    float acc[8];
#pragma unroll
    for (int q = 0; q < 8; q++) acc[q] = 0.f;

    int e = beg;
    for (; e + 4 <= end; e += 4) {
        int s0 = __ldg(&g_csr[e]);
        int s1 = __ldg(&g_csr[e + 1]);
        int s2 = __ldg(&g_csr[e + 2]);
        int s3 = __ldg(&g_csr[e + 3]);
        uint4 v0 = __ldg(xb + (size_t)s0 * STRIDE + t);
        uint4 v1 = __ldg(xb + (size_t)s1 * STRIDE + t);
        uint4 v2 = __ldg(xb + (size_t)s2 * STRIDE + t);
        uint4 v3 = __ldg(xb + (size_t)s3 * STRIDE + t);
        const uint4* vv[4] = {&v0, &v1, &v2, &v3};
#pragma unroll
        for (int j = 0; j < 4; j++) {
            const __half2* h = reinterpret_cast<const __half2*>(vv[j]);
#pragma unroll
            for (int q = 0; q < 4; q++) {
                float2 f = __half22float2(h[q]);
                acc[q * 2]     += f.x;
                acc[q * 2 + 1] += f.y;
            }
        }
    }
    for (; e < end; e++) {
        int s0 = __ldg(&g_csr[e]);
        uint4 v0 = __ldg(xb + (size_t)s0 * STRIDE + t);
        const __half2* h = reinterpret_cast<const __half2*>(&v0);
#pragma unroll
        for (int q = 0; q < 4; q++) {
            float2 f = __half22float2(h[q]);
            acc[q * 2]     += f.x;
            acc[q * 2 + 1] += f.y;
        }
    }
    const float s = g_invdeg[dst];
    __half2 h[4];
#pragma unroll
    for (int q = 0; q < 4; q++)
        h[q] = __floats2half2_rn(acc[q * 2] * s, acc[q * 2 + 1] * s);
    reinterpret_cast<uint4*>(outh)[(size_t)dst * STRIDE + t] = *reinterpret_cast<uint4*>(h);
}

// ---------------- final aggregation: out = mean(yh[src]) + qf[dst] + b3 -------
__global__ void k_agg_final(const __half* __restrict__ yh, const float* __restrict__ qf,
                            const float* __restrict__ bias, float* __restrict__ out, int n) {
    int dst = blockIdx.x;
    if (dst >= n) return;
    const int beg = g_rowptr[dst], end = g_rowptr[dst + 1];
    const int t = threadIdx.x;           // 32 threads, 8 vals each (WIDTH 256)
    const uint4* xb = reinterpret_cast<const uint4*>(yh);
    float acc[8];
#pragma unroll
    for (int q = 0; q < 8; q++) acc[q] = 0.f;

    int e = beg;
    for (; e + 4 <= end; e += 4) {
        int s0 = __ldg(&g_csr[e]);
        int s1 = __ldg(&g_csr[e + 1]);
        int s2 = __ldg(&g_csr[e + 2]);
        int s3 = __ldg(&g_csr[e + 3]);
        uint4 v0 = __ldg(xb + (size_t)s0 * 32 + t);
        uint4 v1 = __ldg(xb + (size_t)s1 * 32 + t);
        uint4 v2 = __ldg(xb + (size_t)s2 * 32 + t);
        uint4 v3 = __ldg(xb + (size_t)s3 * 32 + t);
        const uint4* vv[4] = {&v0, &v1, &v2, &v3};
#pragma unroll
        for (int j = 0; j < 4; j++) {
            const __half2* h = reinterpret_cast<const __half2*>(vv[j]);
#pragma unroll
            for (int q = 0; q < 4; q++) {
                float2 f = __half22float2(h[q]);
                acc[q * 2]     += f.x;
                acc[q * 2 + 1] += f.y;
            }
        }
    }
    for (; e < end; e++) {
        int s0 = __ldg(&g_csr[e]);
        uint4 v0 = __ldg(xb + (size_t)s0 * 32 + t);
        const __half2* h = reinterpret_cast<const __half2*>(&v0);
#pragma unroll
        for (int q = 0; q < 4; q++) {
            float2 f = __half22float2(h[q]);
            acc[q * 2]     += f.x;
            acc[q * 2 + 1] += f.y;
        }
    }
    const float s = g_invdeg[dst];
    const float* qrow = qf + (size_t)dst * 256 + t * 8;
    const float* brow = bias + t * 8;
    float4 q0 = *reinterpret_cast<const float4*>(qrow);
    float4 q1 = *reinterpret_cast<const float4*>(qrow + 4);
    float4 b0 = *reinterpret_cast<const float4*>(brow);
    float4 b1 = *reinterpret_cast<const float4*>(brow + 4);
    float* orow = out + (size_t)dst * 256 + t * 8;
    *reinterpret_cast<float4*>(orow) = make_float4(
        acc[0] * s + q0.x + b0.x, acc[1] * s + q0.y + b0.y,
        acc[2] * s + q0.z + b0.z, acc[3] * s + q0.w + b0.w);
    *reinterpret_cast<float4*>(orow + 4) = make_float4(
        acc[4] * s + q1.x + b1.x, acc[5] * s + q1.y + b1.y,
        acc[6] * s + q1.z + b1.z, acc[7] * s + q1.w + b1.w);
}

// ---------------- fp16 mma.sync GEMM, cp.async 3-stage (proven R8 config) -----
#define STAGES 3
#define GSMEM  (STAGES * 32768)

template <bool DUAL>
__global__ __launch_bounds__(256, 2)
void k_gemm(const __half* __restrict__ A0, const __half* __restrict__ A1,
            const __half* __restrict__ B0, const __half* __restrict__ B1,
            const float* __restrict__ bias,
            const float* __restrict__ gamma, const float* __restrict__ beta,
            const float* __restrict__ mean,  const float* __restrict__ var,
            __half* __restrict__ outh, float* __restrict__ outf,
            int split, int N, int Hdim, int bnrelu)
{
    constexpr int NC = DUAL ? 16 : 8;
    extern __shared__ char smem[];
    const uint32_t sb = smem_u32(smem);
    const int t    = threadIdx.x;
    const int lane = t & 31, wid = t >> 5;
    const int warp_m = wid & 3;
    const int warp_n = wid >> 2;
    const int row0 = blockIdx.x * 128;
    const int col0 = blockIdx.y * 128;

    int lrow[4], lf8[4];
    uint32_t loff[4];
#pragma unroll
    for (int i = 0; i < 4; i++) {
        int idx = t + i * 256;
        lrow[i] = idx >> 3; lf8[i] = idx & 7;
        loff[i] = (uint32_t)lrow[i] * 128 + (uint32_t)((lf8[i] ^ (lrow[i] & 7)) << 4);
    }

    const int rin  = lane & 7;
    const int aGrp = (lane >> 3) & 1, aKhi = (lane >> 4) & 1;
    const int rA0  = warp_m * 32 + aGrp * 8 + rin;
    const uint32_t aO0 = (uint32_t)rA0 * 128;
    const uint32_t aO1 = (uint32_t)(rA0 + 16) * 128;
    const uint32_t aRm = (uint32_t)(rA0 & 7);
    const int bGrp = (lane >> 4) & 1, bKhi = (lane >> 3) & 1;
    const int rB   = warp_n * 64 + bGrp * 8 + rin;
    const uint32_t bRm = (uint32_t)(rB & 7);
    uint32_t bO[4];
#pragma unroll
    for (int p = 0; p < 4; p++) bO[p] = (uint32_t)(rB + p * 16) * 128;

    float d[2][8][4];
#pragma unroll
    for (int mt = 0; mt < 2; mt++)
#pragma unroll
        for (int nt = 0; nt < 8; nt++)
#pragma unroll
            for (int q = 0; q < 4; q++) d[mt][nt][q] = 0.f;

    auto load_stage = [&](int c) {
        const __half* As = (DUAL && c >= 8) ? A1 : A0;
        const __half* Bs = (DUAL && c >= 8) ? B1 : B0;
        const int kk = (c & 7) * 64;
        const uint32_t base = sb + (uint32_t)(c % STAGES) * 32768;
#pragma unroll
        for (int i = 0; i < 4; i++) {
            int gr = min(row0 + lrow[i], N - 1);
            cp16(base + loff[i],         As + (size_t)gr * DK + kk + lf8[i] * 8);
            cp16(base + 16384 + loff[i], Bs + (size_t)(col0 + lrow[i]) * DK + kk + lf8[i] * 8);
        }
        CP_COMMIT();
    };

    load_stage(0);
    load_stage(1);

    for (int c = 0; c < NC; c++) {
        if (c + 1 < NC) { CP_WAIT1(); } else { CP_WAIT0(); }
        __syncthreads();

        const uint32_t Ab = sb + (uint32_t)(c % STAGES) * 32768;
        const uint32_t Bb = Ab + 16384;
#pragma unroll
        for (int ks = 0; ks < 4; ks++) {
            uint32_t a[2][4], b[4][4];
            uint32_t ca = (((uint32_t)(ks * 2 + aKhi) ^ aRm) << 4);
            ldsm_x4(a[0], Ab + aO0 + ca);
            ldsm_x4(a[1], Ab + aO1 + ca);
            uint32_t cb = (((uint32_t)(ks * 2 + bKhi) ^ bRm) << 4);
#pragma unroll
            for (int p = 0; p < 4; p++) ldsm_x4(b[p], Bb + bO[p] + cb);
#pragma unroll
            for (int mt = 0; mt < 2; mt++)
#pragma unroll
                for (int p = 0; p < 4; p++) {
                    mma_f16(d[mt][p * 2 + 0], a[mt], &b[p][0]);
                    mma_f16(d[mt][p * 2 + 1], a[mt], &b[p][2]);
                }
        }
        if (c + 2 < NC) load_stage(c + 2);
    }

    const int g  = lane >> 2;
    const int cp = (lane & 3) * 2;
    const bool splitF32 = (split > 0) && (col0 >= split);   // uniform per CTA
    const int ostride = (split > 0) ? split : Hdim;
#pragma unroll
    for (int nt = 0; nt < 8; nt++) {
        const int gc = col0 + warp_n * 64 + nt * 8 + cp;
        float s0 = 1.f, s1 = 1.f, h0 = bias[gc], h1 = bias[gc + 1];
        if (bnrelu) {
            float r0 = gamma[gc]     * rsqrtf(var[gc]     + 1e-5f);
            float r1 = gamma[gc + 1] * rsqrtf(var[gc + 1] + 1e-5f);
            h0 = (h0 - mean[gc])     * r0 + beta[gc];
            h1 = (h1 - mean[gc + 1]) * r1 + beta[gc + 1];
            s0 = r0; s1 = r1;
        }
        const int oc = splitF32 ? (gc - split) : gc;
#pragma unroll
        for (int mt = 0; mt < 2; mt++) {
            const int r_lo = row0 + warp_m * 32 + mt * 16 + g;
            const int r_hi = r_lo + 8;
            float v0 = d[mt][nt][0] * s0 + h0;
            float v1 = d[mt][nt][1] * s1 + h1;
            float v2 = d[mt][nt][2] * s0 + h0;
            float v3 = d[mt][nt][3] * s1 + h1;
            if (bnrelu) {
                v0 = fmaxf(v0, 0.f); v1 = fmaxf(v1, 0.f);
                v2 = fmaxf(v2, 0.f); v3 = fmaxf(v3, 0.f);
            }
            if (splitF32) {
                if (r_lo < N)
                    *reinterpret_cast<float2*>(outf + (size_t)r_lo * ostride + oc) = make_float2(v0, v1);
                if (r_hi < N)
                    *reinterpret_cast<float2*>(outf + (size_t)r_hi * ostride + oc) = make_float2(v2, v3);
            } else {
                if (r_lo < N)
                    *reinterpret_cast<__half2*>(outh + (size_t)r_lo * ostride + oc) = __floats2half2_rn(v0, v1);
                if (r_hi < N)
                    *reinterpret_cast<__half2*>(outh + (size_t)r_hi * ostride + oc) = __floats2half2_rn(v2, v3);
            }
        }
    }
}

// ---------------- launch ------------------------------------------------------
extern "C" void kernel_launch(void* const* d_in, const int* in_sizes, int n_in,
                              void* d_out, int out_size)
{
    const float* x     = (const float*)d_in[0];
    const int*   ei    = (const int*)  d_in[1];
    const float* w_l1  = (const float*)d_in[2];
    const float* b1    = (const float*)d_in[3];
    const float* w_r1  = (const float*)d_in[4];
    const float* bn1_g = (const float*)d_in[5];
    const float* bn1_b = (const float*)d_in[6];
    const float* bn1_m = (const float*)d_in[7];
    const float* bn1_v = (const float*)d_in[8];
    const float* w_l2  = (const float*)d_in[9];
    const float* b2    = (const float*)d_in[10];
    const float* w_r2  = (const float*)d_in[11];
    const float* bn2_g = (const float*)d_in[12];
    const float* bn2_b = (const float*)d_in[13];
    const float* bn2_m = (const float*)d_in[14];
    const float* bn2_v = (const float*)d_in[15];
    const float* w_l3  = (const float*)d_in[16];
    const float* b3    = (const float*)d_in[17];
    const float* w_r3  = (const float*)d_in[18];
    float* out = (float*)d_out;

    const int N = in_sizes[0] / DK;
    const int E = in_sizes[1] / 2;
    const int O = out_size / N;   // 256

    __half *xh, *aggh, *h1h, *h2h, *yh, *wth;
    float *qf, *zero;
    cudaGetSymbolAddress((void**)&xh,   g_xh);
    cudaGetSymbolAddress((void**)&aggh, g_aggh);
    cudaGetSymbolAddress((void**)&h1h,  g_h1h);
    cudaGetSymbolAddress((void**)&h2h,  g_h2h);
    cudaGetSymbolAddress((void**)&yh,   g_yh);
    cudaGetSymbolAddress((void**)&qf,   g_qf);
    cudaGetSymbolAddress((void**)&wth,  g_wth);
    cudaGetSymbolAddress((void**)&zero, g_zero);
    __half* wlt1 = wth;
    __half* wrt1 = wth + 512 * 512;
    __half* wlt2 = wth + 2 * 512 * 512;
    __half* wrt2 = wth + 3 * 512 * 512;
    __half* wlt3 = wth + 4 * 512 * 512;             // rows 0-255 of wide B
    __half* wrt3 = wth + 4 * 512 * 512 + 256 * 512; // rows 256-511 (contiguous)

    cudaFuncSetAttribute(k_gemm<true>,  cudaFuncAttributeMaxDynamicSharedMemorySize, GSMEM);
    cudaFuncSetAttribute(k_gemm<false>, cudaFuncAttributeMaxDynamicSharedMemorySize, GSMEM);

    const int n8 = N * DK / 8;
    const int nfill = (max(E, n8) + 255) / 256;

    // 1-3: CSR build + x->fp16 + weight transposes
    k_deg <<<(E + 255) / 256, 256>>>(ei, E);
    k_scan<<<1, 1024>>>(N);
    TP6 tps = {{ {w_l1, wlt1, 512}, {w_r1, wrt1, 512},
                 {w_l2, wlt2, 512}, {w_r2, wrt2, 512},
                 {w_l3, wlt3, 256}, {w_r3, wrt3, 256} }};
    k_setup<<<nfill + 6 * 256, 256>>>(ei, E, N, x, xh, n8, nfill, tps);

    // 4 (profiled): aggregation layer 1
    k_agg<512><<<N, 64>>>(xh, aggh, N);

    const int mt = (N + 127) / 128;
    dim3 gH(mt, 512 / 128);

    // 5: layer 1
    k_gemm<true><<<gH, 256, GSMEM>>>(aggh, xh, wlt1, wrt1, b1,
                                     bn1_g, bn1_b, bn1_m, bn1_v,
                                     h1h, nullptr, 0, N, 512, 1);
    // 6-7: layer 2
    k_agg<512><<<N, 64>>>(h1h, aggh, N);
    k_gemm<true><<<gH, 256, GSMEM>>>(aggh, h1h, wlt2, wrt2, b2,
                                     bn2_g, bn2_b, bn2_m, bn2_v,
                                     h2h, nullptr, 0, N, 512, 1);
    // 8: layer 3 wide projection: [yh | qf] = h2 @ [wl3 | wr3]
    k_gemm<false><<<gH, 256, GSMEM>>>(h2h, nullptr, wlt3, nullptr, zero,
                                      zero, zero, zero, zero,
                                      yh, qf, 256, N, 512, 0);
    // 9: out = mean-agg(yh) + qf + b3
    k_agg_final<<<N, 32>>>(yh, qf, b3, out, N);
}

// round 17
// speedup vs baseline: 2.0988x; 1.0353x over previous
#include <cuda_runtime.h>
#include <cuda_fp16.h>
#include <cstdint>

#define DK 512
#define MAXN 10048
#define MAXE 161000

// ---------------- scratch ----------------------------------------------------
__device__ int    g_deg[MAXN];          // static zero-init; setup re-zeroes
__device__ int    g_rowptr[MAXN + 1];
__device__ int    g_cursor[MAXN];
__device__ int    g_csr[MAXE];
__device__ float  g_invdeg[MAXN];
__device__ __half g_xh  [(size_t)MAXN * DK];   // fp16 x
__device__ __half g_aggh[(size_t)MAXN * DK];   // fp16 aggregate (L1/L2)
__device__ __half g_h1h [(size_t)MAXN * DK];
__device__ __half g_h2h [(size_t)MAXN * DK];
__device__ __half g_yh  [(size_t)MAXN * 256];  // layer-3: h2@wl3 (fp16)
__device__ float  g_qf  [(size_t)MAXN * 256];  // layer-3: h2@wr3 (fp32)
__device__ __half g_wth[4 * 512 * 512 + 2 * 256 * 512];
__device__ float  g_zero[512];                 // static zeros (never written)

// ---------------- helpers ------------------------------------------------
__device__ __forceinline__ uint32_t smem_u32(const void* p) {
    uint32_t a;
    asm("{ .reg .u64 t; cvta.to.shared.u64 t, %1; cvt.u32.u64 %0, t; }" : "=r"(a) : "l"(p));
    return a;
}
__device__ __forceinline__ void ldsm_x4(uint32_t* r, uint32_t addr) {
    asm volatile("ldmatrix.sync.aligned.m8n8.x4.shared.b16 {%0,%1,%2,%3}, [%4];"
                 : "=r"(r[0]), "=r"(r[1]), "=r"(r[2]), "=r"(r[3]) : "r"(addr));
}
__device__ __forceinline__ void mma_f16(float* d, const uint32_t* a, const uint32_t* b) {
    asm volatile("mma.sync.aligned.m16n8k16.row.col.f32.f16.f16.f32 "
                 "{%0,%1,%2,%3}, {%4,%5,%6,%7}, {%8,%9}, {%0,%1,%2,%3};"
                 : "+f"(d[0]), "+f"(d[1]), "+f"(d[2]), "+f"(d[3])
                 : "r"(a[0]), "r"(a[1]), "r"(a[2]), "r"(a[3]), "r"(b[0]), "r"(b[1]));
}
__device__ __forceinline__ void cp16(uint32_t dst, const void* src) {
    asm volatile("cp.async.cg.shared.global [%0], [%1], 16;" :: "r"(dst), "l"(src));
}
#define CP_COMMIT() asm volatile("cp.async.commit_group;" ::: "memory")
#define CP_WAIT1()  asm volatile("cp.async.wait_group 1;" ::: "memory")
#define CP_WAIT0()  asm volatile("cp.async.wait_group 0;" ::: "memory")

// ---------------- CSR build --------------------------------------------------
__global__ void k_deg(const int* __restrict__ ei, int E) {
    int e = blockIdx.x * blockDim.x + threadIdx.x;
    if (e < E) atomicAdd(&g_deg[ei[E + e]], 1);
}
__global__ void k_scan(int n) {
    __shared__ int ws[32];
    __shared__ int s_carry;
    const int t = threadIdx.x, lane = t & 31, w = t >> 5;
    if (t == 0) s_carry = 0;
    __syncthreads();
    for (int base = 0; base < n; base += 1024) {
        int idx = base + t;
        int v = (idx < n) ? g_deg[idx] : 0;
        int sc = v;
#pragma unroll
        for (int o = 1; o < 32; o <<= 1) {
            int u = __shfl_up_sync(0xffffffffu, sc, o);
            if (lane >= o) sc += u;
        }
        if (lane == 31) ws[w] = sc;
        __syncthreads();
        if (w == 0) {
            int x2 = ws[lane];
#pragma unroll
            for (int o = 1; o < 32; o <<= 1) {
                int u = __shfl_up_sync(0xffffffffu, x2, o);
                if (lane >= o) x2 += u;
            }
            ws[lane] = x2;
        }
        __syncthreads();
        int carry = s_carry;
        int add = carry + (w ? ws[w - 1] : 0);
        if (idx < n) {
            g_rowptr[idx] = add + sc - v;
            g_invdeg[idx] = 1.0f / (float)max(v, 1);
            g_cursor[idx] = 0;
        }
        __syncthreads();
        if (t == 0) s_carry = carry + ws[31];
        __syncthreads();
    }
    if (t == 0) g_rowptr[n] = s_carry;
}

// ---------------- merged setup: CSR fill + deg re-zero + x->fp16 + transposes -
struct TP { const float* W; __half* WT; int H; };
struct TP6 { TP m[6]; };
__global__ void k_setup(const int* __restrict__ ei, int E, int n,
                        const float* __restrict__ x, __half* __restrict__ xh, int n8,
                        int nfill, TP6 tps) {
    __shared__ float tile[32][33];
    const int b = blockIdx.x;
    if (b < nfill) {
        int i = b * 256 + threadIdx.x;
        if (i < n) g_deg[i] = 0;   // restore invariant for next replay
        if (i < E) {
            int d = ei[E + i];
            int pos = atomicAdd(&g_cursor[d], 1);
            g_csr[g_rowptr[d] + pos] = ei[i];
        }
        if (i < n8) {
            float4 lo = reinterpret_cast<const float4*>(x)[i * 2];
            float4 hi = reinterpret_cast<const float4*>(x)[i * 2 + 1];
            __half2 h[4];
            h[0] = __floats2half2_rn(lo.x, lo.y);
            h[1] = __floats2half2_rn(lo.z, lo.w);
            h[2] = __floats2half2_rn(hi.x, hi.y);
            h[3] = __floats2half2_rn(hi.z, hi.w);
            reinterpret_cast<uint4*>(xh)[i] = *reinterpret_cast<uint4*>(h);
        }
    } else {
        const int tb = b - nfill;          // 0..1535
        const TP tp = tps.m[tb >> 8];
        const int H = tp.H;
        const int k0 = (tb & 15) * 32, h0 = ((tb >> 4) & 15) * 32;
        if (h0 >= H) return;
        const int tx = threadIdx.x & 31, ty = threadIdx.x >> 5;   // 32 x 8
#pragma unroll
        for (int i = 0; i < 32; i += 8)
            tile[ty + i][tx] = tp.W[(size_t)(k0 + ty + i) * H + h0 + tx];
        __syncthreads();
#pragma unroll
        for (int i = 0; i < 32; i += 8)
            tp.WT[(size_t)(h0 + ty + i) * DK + k0 + tx] = __float2half_rn(tile[tx][ty + i]);
    }
}

// ---------------- aggregation: fp16 input, fp32 accumulate (proven 16.5us) ----
template <int WIDTH>
__global__ void k_agg(const __half* __restrict__ x, __half* __restrict__ outh, int n) {
    int dst = blockIdx.x;
    if (dst >= n) return;
    const int beg = g_rowptr[dst], end = g_rowptr[dst + 1];
    const int t = threadIdx.x;
    constexpr int STRIDE = WIDTH / 8;
    const uint4* xb = reinterpret_cast<const uint4*>(x);
    float acc[8];
#pragma unroll
    for (int q = 0; q < 8; q++) acc[q] = 0.f;

    int e = beg;
    for (; e + 4 <= end; e += 4) {
        int s0 = __ldg(&g_csr[e]);
        int s1 = __ldg(&g_csr[e + 1]);
        int s2 = __ldg(&g_csr[e + 2]);
        int s3 = __ldg(&g_csr[e + 3]);
        uint4 v0 = __ldg(xb + (size_t)s0 * STRIDE + t);
        uint4 v1 = __ldg(xb + (size_t)s1 * STRIDE + t);
        uint4 v2 = __ldg(xb + (size_t)s2 * STRIDE + t);
        uint4 v3 = __ldg(xb + (size_t)s3 * STRIDE + t);
        const uint4* vv[4] = {&v0, &v1, &v2, &v3};
#pragma unroll
        for (int j = 0; j < 4; j++) {
            const __half2* h = reinterpret_cast<const __half2*>(vv[j]);
#pragma unroll
            for (int q = 0; q < 4; q++) {
                float2 f = __half22float2(h[q]);
                acc[q * 2]     += f.x;
                acc[q * 2 + 1] += f.y;
            }
        }
    }
    for (; e < end; e++) {
        int s0 = __ldg(&g_csr[e]);
        uint4 v0 = __ldg(xb + (size_t)s0 * STRIDE + t);
        const __half2* h = reinterpret_cast<const __half2*>(&v0);
#pragma unroll
        for (int q = 0; q < 4; q++) {
            float2 f = __half22float2(h[q]);
            acc[q * 2]     += f.x;
            acc[q * 2 + 1] += f.y;
        }
    }
    const float s = g_invdeg[dst];
    __half2 h[4];
#pragma unroll
    for (int q = 0; q < 4; q++)
        h[q] = __floats2half2_rn(acc[q * 2] * s, acc[q * 2 + 1] * s);
    reinterpret_cast<uint4*>(outh)[(size_t)dst * STRIDE + t] = *reinterpret_cast<uint4*>(h);
}

// ---------------- final aggregation: out = mean(yh[src]) + qf[dst] + b3 -------
__global__ void k_agg_final(const __half* __restrict__ yh, const float* __restrict__ qf,
                            const float* __restrict__ bias, float* __restrict__ out, int n) {
    int dst = blockIdx.x;
    if (dst >= n) return;
    const int beg = g_rowptr[dst], end = g_rowptr[dst + 1];
    const int t = threadIdx.x;           // 32 threads, 8 vals each (WIDTH 256)
    const uint4* xb = reinterpret_cast<const uint4*>(yh);
    float acc[8];
#pragma unroll
    for (int q = 0; q < 8; q++) acc[q] = 0.f;

    int e = beg;
    for (; e + 4 <= end; e += 4) {
        int s0 = __ldg(&g_csr[e]);
        int s1 = __ldg(&g_csr[e + 1]);
        int s2 = __ldg(&g_csr[e + 2]);
        int s3 = __ldg(&g_csr[e + 3]);
        uint4 v0 = __ldg(xb + (size_t)s0 * 32 + t);
        uint4 v1 = __ldg(xb + (size_t)s1 * 32 + t);
        uint4 v2 = __ldg(xb + (size_t)s2 * 32 + t);
        uint4 v3 = __ldg(xb + (size_t)s3 * 32 + t);
        const uint4* vv[4] = {&v0, &v1, &v2, &v3};
#pragma unroll
        for (int j = 0; j < 4; j++) {
            const __half2* h = reinterpret_cast<const __half2*>(vv[j]);
#pragma unroll
            for (int q = 0; q < 4; q++) {
                float2 f = __half22float2(h[q]);
                acc[q * 2]     += f.x;
                acc[q * 2 + 1] += f.y;
            }
        }
    }
    for (; e < end; e++) {
        int s0 = __ldg(&g_csr[e]);
        uint4 v0 = __ldg(xb + (size_t)s0 * 32 + t);
        const __half2* h = reinterpret_cast<const __half2*>(&v0);
#pragma unroll
        for (int q = 0; q < 4; q++) {
            float2 f = __half22float2(h[q]);
            acc[q * 2]     += f.x;
            acc[q * 2 + 1] += f.y;
        }
    }
    const float s = g_invdeg[dst];
    const float* qrow = qf + (size_t)dst * 256 + t * 8;
    const float* brow = bias + t * 8;
    float4 q0 = *reinterpret_cast<const float4*>(qrow);
    float4 q1 = *reinterpret_cast<const float4*>(qrow + 4);
    float4 b0 = *reinterpret_cast<const float4*>(brow);
    float4 b1 = *reinterpret_cast<const float4*>(brow + 4);
    float* orow = out + (size_t)dst * 256 + t * 8;
    *reinterpret_cast<float4*>(orow) = make_float4(
        acc[0] * s + q0.x + b0.x, acc[1] * s + q0.y + b0.y,
        acc[2] * s + q0.z + b0.z, acc[3] * s + q0.w + b0.w);
    *reinterpret_cast<float4*>(orow + 4) = make_float4(
        acc[4] * s + q1.x + b1.x, acc[5] * s + q1.y + b1.y,
        acc[6] * s + q1.z + b1.z, acc[7] * s + q1.w + b1.w);
}

// ---------------- fp16 mma.sync GEMM: 128x64 CTA tile, 3 CTAs/SM --------------
// 8 warps (4 warp_m x 2 warp_n); each warp: 32 rows x 32 cols.
// Stage = 16KB A + 8KB B = 24KB; 3 stages = 72KB.
#define STAGES 3
#define STAGEB 24576
#define GSMEM  (STAGES * STAGEB)

template <bool DUAL>
__global__ __launch_bounds__(256, 3)
void k_gemm(const __half* __restrict__ A0, const __half* __restrict__ A1,
            const __half* __restrict__ B0, const __half* __restrict__ B1,
            const float* __restrict__ bias,
            const float* __restrict__ gamma, const float* __restrict__ beta,
            const float* __restrict__ mean,  const float* __restrict__ var,
            __half* __restrict__ outh, float* __restrict__ outf,
            int split, int N, int Hdim, int bnrelu)
{
    constexpr int NC = DUAL ? 16 : 8;
    extern __shared__ char smem[];
    const uint32_t sb = smem_u32(smem);
    const int t    = threadIdx.x;
    const int lane = t & 31, wid = t >> 5;
    const int warp_m = wid & 3;          // 4 warps x 32 rows
    const int warp_n = wid >> 2;         // 2 warps x 32 cols
    const int row0 = blockIdx.x * 128;
    const int col0 = blockIdx.y * 64;

    // A loads: 4 x 16B per thread (1024 chunks); B loads: 2 x 16B (512 chunks)
    int arow[4], af8[4];
    uint32_t aoff[4];
#pragma unroll
    for (int i = 0; i < 4; i++) {
        int idx = t + i * 256;
        arow[i] = idx >> 3; af8[i] = idx & 7;
        aoff[i] = (uint32_t)arow[i] * 128 + (uint32_t)((af8[i] ^ (arow[i] & 7)) << 4);
    }
    int brow[2], bf8[2];
    uint32_t boff[2];
#pragma unroll
    for (int i = 0; i < 2; i++) {
        int idx = t + i * 256;
        brow[i] = idx >> 3; bf8[i] = idx & 7;
        boff[i] = (uint32_t)brow[i] * 128 + (uint32_t)((bf8[i] ^ (brow[i] & 7)) << 4);
    }

    // ldmatrix addressing (same algebra as proven kernel)
    const int rin  = lane & 7;
    const int aGrp = (lane >> 3) & 1, aKhi = (lane >> 4) & 1;
    const int rA0  = warp_m * 32 + aGrp * 8 + rin;
    const uint32_t aO0 = (uint32_t)rA0 * 128;
    const uint32_t aO1 = (uint32_t)(rA0 + 16) * 128;
    const uint32_t aRm = (uint32_t)(rA0 & 7);
    const int bGrp = (lane >> 4) & 1, bKhi = (lane >> 3) & 1;
    const int rB   = warp_n * 32 + bGrp * 8 + rin;
    const uint32_t bRm = (uint32_t)(rB & 7);
    uint32_t bO[2];
#pragma unroll
    for (int p = 0; p < 2; p++) bO[p] = (uint32_t)(rB + p * 16) * 128;

    float d[2][4][4];
#pragma unroll
    for (int mt = 0; mt < 2; mt++)
#pragma unroll
        for (int nt = 0; nt < 4; nt++)
#pragma unroll
            for (int q = 0; q < 4; q++) d[mt][nt][q] = 0.f;

    auto load_stage = [&](int c) {
        const __half* As = (DUAL && c >= 8) ? A1 : A0;
        const __half* Bs = (DUAL && c >= 8) ? B1 : B0;
        const int kk = (c & 7) * 64;
        const uint32_t base = sb + (uint32_t)(c % STAGES) * STAGEB;
#pragma unroll
        for (int i = 0; i < 4; i++) {
            int gr = min(row0 + arow[i], N - 1);
            cp16(base + aoff[i], As + (size_t)gr * DK + kk + af8[i] * 8);
        }
#pragma unroll
        for (int i = 0; i < 2; i++)
            cp16(base + 16384 + boff[i], Bs + (size_t)(col0 + brow[i]) * DK + kk + bf8[i] * 8);
        CP_COMMIT();
    };

    load_stage(0);
    load_stage(1);

    for (int c = 0; c < NC; c++) {
        if (c + 1 < NC) { CP_WAIT1(); } else { CP_WAIT0(); }
        __syncthreads();

        const uint32_t Ab = sb + (uint32_t)(c % STAGES) * STAGEB;
        const uint32_t Bb = Ab + 16384;
#pragma unroll
        for (int ks = 0; ks < 4; ks++) {
            uint32_t a[2][4], b[2][4];
            uint32_t ca = (((uint32_t)(ks * 2 + aKhi) ^ aRm) << 4);
            ldsm_x4(a[0], Ab + aO0 + ca);
            ldsm_x4(a[1], Ab + aO1 + ca);
            uint32_t cb = (((uint32_t)(ks * 2 + bKhi) ^ bRm) << 4);
#pragma unroll
            for (int p = 0; p < 2; p++) ldsm_x4(b[p], Bb + bO[p] + cb);
#pragma unroll
            for (int mt = 0; mt < 2; mt++)
#pragma unroll
                for (int p = 0; p < 2; p++) {
                    mma_f16(d[mt][p * 2 + 0], a[mt], &b[p][0]);
                    mma_f16(d[mt][p * 2 + 1], a[mt], &b[p][2]);
                }
        }
        if (c + 2 < NC) load_stage(c + 2);
    }

    const int g  = lane >> 2;
    const int cp = (lane & 3) * 2;
    const bool splitF32 = (split > 0) && (col0 >= split);   // uniform per CTA
    const int ostride = (split > 0) ? split : Hdim;
#pragma unroll
    for (int nt = 0; nt < 4; nt++) {
        const int gc = col0 + warp_n * 32 + nt * 8 + cp;
        float s0 = 1.f, s1 = 1.f, h0 = bias[gc], h1 = bias[gc + 1];
        if (bnrelu) {
            float r0 = gamma[gc]     * rsqrtf(var[gc]     + 1e-5f);
            float r1 = gamma[gc + 1] * rsqrtf(var[gc + 1] + 1e-5f);
            h0 = (h0 - mean[gc])     * r0 + beta[gc];
            h1 = (h1 - mean[gc + 1]) * r1 + beta[gc + 1];
            s0 = r0; s1 = r1;
        }
        const int oc = splitF32 ? (gc - split) : gc;
#pragma unroll
        for (int mt = 0; mt < 2; mt++) {
            const int r_lo = row0 + warp_m * 32 + mt * 16 + g;
            const int r_hi = r_lo + 8;
            float v0 = d[mt][nt][0] * s0 + h0;
            float v1 = d[mt][nt][1] * s1 + h1;
            float v2 = d[mt][nt][2] * s0 + h0;
            float v3 = d[mt][nt][3] * s1 + h1;
            if (bnrelu) {
                v0 = fmaxf(v0, 0.f); v1 = fmaxf(v1, 0.f);
                v2 = fmaxf(v2, 0.f); v3 = fmaxf(v3, 0.f);
            }
            if (splitF32) {
                if (r_lo < N)
                    *reinterpret_cast<float2*>(outf + (size_t)r_lo * ostride + oc) = make_float2(v0, v1);
                if (r_hi < N)
                    *reinterpret_cast<float2*>(outf + (size_t)r_hi * ostride + oc) = make_float2(v2, v3);
            } else {
                if (r_lo < N)
                    *reinterpret_cast<__half2*>(outh + (size_t)r_lo * ostride + oc) = __floats2half2_rn(v0, v1);
                if (r_hi < N)
                    *reinterpret_cast<__half2*>(outh + (size_t)r_hi * ostride + oc) = __floats2half2_rn(v2, v3);
            }
        }
    }
}

// ---------------- launch ------------------------------------------------------
extern "C" void kernel_launch(void* const* d_in, const int* in_sizes, int n_in,
                              void* d_out, int out_size)
{
    const float* x     = (const float*)d_in[0];
    const int*   ei    = (const int*)  d_in[1];
    const float* w_l1  = (const float*)d_in[2];
    const float* b1    = (const float*)d_in[3];
    const float* w_r1  = (const float*)d_in[4];
    const float* bn1_g = (const float*)d_in[5];
    const float* bn1_b = (const float*)d_in[6];
    const float* bn1_m = (const float*)d_in[7];
    const float* bn1_v = (const float*)d_in[8];
    const float* w_l2  = (const float*)d_in[9];
    const float* b2    = (const float*)d_in[10];
    const float* w_r2  = (const float*)d_in[11];
    const float* bn2_g = (const float*)d_in[12];
    const float* bn2_b = (const float*)d_in[13];
    const float* bn2_m = (const float*)d_in[14];
    const float* bn2_v = (const float*)d_in[15];
    const float* w_l3  = (const float*)d_in[16];
    const float* b3    = (const float*)d_in[17];
    const float* w_r3  = (const float*)d_in[18];
    float* out = (float*)d_out;

    const int N = in_sizes[0] / DK;
    const int E = in_sizes[1] / 2;
    const int O = out_size / N;   // 256

    __half *xh, *aggh, *h1h, *h2h, *yh, *wth;
    float *qf, *zero;
    cudaGetSymbolAddress((void**)&xh,   g_xh);
    cudaGetSymbolAddress((void**)&aggh, g_aggh);
    cudaGetSymbolAddress((void**)&h1h,  g_h1h);
    cudaGetSymbolAddress((void**)&h2h,  g_h2h);
    cudaGetSymbolAddress((void**)&yh,   g_yh);
    cudaGetSymbolAddress((void**)&qf,   g_qf);
    cudaGetSymbolAddress((void**)&wth,  g_wth);
    cudaGetSymbolAddress((void**)&zero, g_zero);
    __half* wlt1 = wth;
    __half* wrt1 = wth + 512 * 512;
    __half* wlt2 = wth + 2 * 512 * 512;
    __half* wrt2 = wth + 3 * 512 * 512;
    __half* wlt3 = wth + 4 * 512 * 512;             // rows 0-255 of wide B
    __half* wrt3 = wth + 4 * 512 * 512 + 256 * 512; // rows 256-511 (contiguous)

    cudaFuncSetAttribute(k_gemm<true>,  cudaFuncAttributeMaxDynamicSharedMemorySize, GSMEM);
    cudaFuncSetAttribute(k_gemm<false>, cudaFuncAttributeMaxDynamicSharedMemorySize, GSMEM);

    const int n8 = N * DK / 8;
    const int nfill = (max(E, n8) + 255) / 256;

    // 1-3: CSR build + x->fp16 + weight transposes
    k_deg <<<(E + 255) / 256, 256>>>(ei, E);
    k_scan<<<1, 1024>>>(N);
    TP6 tps = {{ {w_l1, wlt1, 512}, {w_r1, wrt1, 512},
                 {w_l2, wlt2, 512}, {w_r2, wrt2, 512},
                 {w_l3, wlt3, 256}, {w_r3, wrt3, 256} }};
    k_setup<<<nfill + 6 * 256, 256>>>(ei, E, N, x, xh, n8, nfill, tps);

    // 4 (profiled): aggregation layer 1
    k_agg<512><<<N, 64>>>(xh, aggh, N);

    const int mt = (N + 127) / 128;
    dim3 gH(mt, 512 / 64);   // 79 x 8 = 632 CTAs

    // 5: layer 1
    k_gemm<true><<<gH, 256, GSMEM>>>(aggh, xh, wlt1, wrt1, b1,
                                     bn1_g, bn1_b, bn1_m, bn1_v,
                                     h1h, nullptr, 0, N, 512, 1);
    // 6-7: layer 2
    k_agg<512><<<N, 64>>>(h1h, aggh, N);
    k_gemm<true><<<gH, 256, GSMEM>>>(aggh, h1h, wlt2, wrt2, b2,
                                     bn2_g, bn2_b, bn2_m, bn2_v,
                                     h2h, nullptr, 0, N, 512, 1);
    // 8: layer 3 wide projection: [yh | qf] = h2 @ [wl3 | wr3]
    k_gemm<false><<<gH, 256, GSMEM>>>(h2h, nullptr, wlt3, nullptr, zero,
                                      zero, zero, zero, zero,
                                      yh, qf, 256, N, 512, 0);
    // 9: out = mean-agg(yh) + qf + b3
    k_agg_final<<<N, 32>>>(yh, qf, b3, out, N);
}